// round 17
// baseline (speedup 1.0000x reference)
#include <cuda_runtime.h>
#include <cuda_fp16.h>
#include <cstdint>

#define NN 100000
#define EE 1600000
#define SCAN_BLK 1024
#define SCAN_NB ((NN + SCAN_BLK - 1) / SCAN_BLK)   // 98

#define SCL 256.0f      // fp16 storage scale for agg/mid tensors (power of two: exact)
#define SCLI (1.0f / 256.0f)

// ---------------- scratch (no allocations allowed) ----------------
__device__ int    g_is64;
__device__ int    g_deg[NN];
__device__ int    g_off[NN];
__device__ int    g_cur[NN];
__device__ int    g_csr[EE];
__device__ int    g_part[128];
__device__ int    g_partoff[128];
__device__ float  g_x[NN * 128];     // final layer fp32 out (fc/emb source)
__device__ __half g_xh[NN * 128];    // activation buffer A (fp16, unscaled)
__device__ __half g_yh[NN * 128];    // activation buffer B (fp16, unscaled)
__device__ __half g_wh[69632];       // fp16 weights: W1a|W1b|W2a|W2b|W3a|W3b

__device__ __forceinline__ __half* abuf(int i) { return (i == 0) ? g_xh : g_yh; }

// ---------------- detect dtype + zero degree (merged) ----------------
__global__ void k_detect(const long long* __restrict__ e64) {
    int i = blockIdx.x * blockDim.x + threadIdx.x;
    if (i < NN) g_deg[i] = 0;
    if (blockIdx.x == 0) {
        __shared__ int bad;
        if (threadIdx.x == 0) bad = 0;
        __syncthreads();
        for (int k = threadIdx.x; k < 4096; k += blockDim.x) {
            long long v = e64[k];
            if (v < 0 || v >= NN) bad = 1;
        }
        __syncthreads();
        if (threadIdx.x == 0) g_is64 = bad ? 0 : 1;
    }
}

__device__ __forceinline__ int edge_at(const void* ei, int idx) {
    if (g_is64) return (int)((const long long*)ei)[idx];
    return ((const int*)ei)[idx];
}

__global__ void k_hist(const void* __restrict__ ei) {
    int e = blockIdx.x * blockDim.x + threadIdx.x;
    if (e < EE) {
        int d = edge_at(ei, EE + e);
        if ((unsigned)d < (unsigned)NN) atomicAdd(&g_deg[d], 1);
    }
}

__global__ void k_block_sums() {
    int i = blockIdx.x * SCAN_BLK + threadIdx.x;
    int v = (i < NN) ? g_deg[i] : 0;
    #pragma unroll
    for (int o = 16; o > 0; o >>= 1) v += __shfl_down_sync(0xffffffffu, v, o);
    __shared__ int ws[32];
    int wid = threadIdx.x >> 5, lane = threadIdx.x & 31;
    if (lane == 0) ws[wid] = v;
    __syncthreads();
    if (wid == 0) {
        int s = ws[lane];
        #pragma unroll
        for (int o = 16; o > 0; o >>= 1) s += __shfl_down_sync(0xffffffffu, s, o);
        if (lane == 0) g_part[blockIdx.x] = s;
    }
}

__global__ void k_scan_parts() {
    __shared__ int sm[128];
    int t = threadIdx.x;
    int v = (t < SCAN_NB) ? g_part[t] : 0;
    sm[t] = v;
    __syncthreads();
    #pragma unroll
    for (int o = 1; o < 128; o <<= 1) {
        int u = (t >= o) ? sm[t - o] : 0;
        __syncthreads();
        sm[t] += u;
        __syncthreads();
    }
    g_partoff[t] = sm[t] - v;   // exclusive
}

__global__ void k_scan_final() {
    int i = blockIdx.x * SCAN_BLK + threadIdx.x;
    int v = (i < NN) ? g_deg[i] : 0;
    int wid = threadIdx.x >> 5, lane = threadIdx.x & 31;
    int incl = v;
    #pragma unroll
    for (int o = 1; o < 32; o <<= 1) {
        int u = __shfl_up_sync(0xffffffffu, incl, o);
        if (lane >= o) incl += u;
    }
    __shared__ int ws[32];
    if (lane == 31) ws[wid] = incl;
    __syncthreads();
    if (wid == 0) {
        int s = ws[lane];
        #pragma unroll
        for (int o = 1; o < 32; o <<= 1) {
            int u = __shfl_up_sync(0xffffffffu, s, o);
            if (lane >= o) s += u;
        }
        ws[lane] = s - ws[lane];
    }
    __syncthreads();
    if (i < NN) {
        int e = incl - v + ws[wid] + g_partoff[blockIdx.x];
        g_off[i] = e;
        g_cur[i] = e;
    }
}

__global__ void k_fill(const void* __restrict__ ei) {
    int e = blockIdx.x * blockDim.x + threadIdx.x;
    if (e < EE) {
        int d = edge_at(ei, EE + e);
        int s = edge_at(ei, e);
        if ((unsigned)d < (unsigned)NN && (unsigned)s < (unsigned)NN) {
            int p = atomicAdd(&g_cur[d], 1);
            if ((unsigned)p < (unsigned)EE) g_csr[p] = s;
        }
    }
}

// ---------------- x (fp32) -> g_xh (fp16) for layer-1 gather ----------------
__global__ void k_x2h(const float* __restrict__ x) {
    int i = blockIdx.x * blockDim.x + threadIdx.x;
    if (i < NN * 32) {
        float2 f = ((const float2*)x)[i];
        ((__half2*)g_xh)[i] = __floats2half2_rn(f.x, f.y);
    }
}

// ---------------- weights fp32 -> fp16 (once per launch) ----------------
__global__ void k_w2h(const float* __restrict__ W1a, const float* __restrict__ W1b,
                      const float* __restrict__ W2a, const float* __restrict__ W2b,
                      const float* __restrict__ W3a, const float* __restrict__ W3b) {
    int i = blockIdx.x * blockDim.x + threadIdx.x;
    if (i >= 69632) return;
    float v;
    if      (i < 8192)  v = W1a[i];
    else if (i < 24576) v = W1b[i - 8192];
    else if (i < 40960) v = W2a[i - 24576];
    else if (i < 57344) v = W2b[i - 40960];
    else if (i < 65536) v = W3a[i - 57344];
    else                v = W3b[i - 65536];
    g_wh[i] = __float2half(v);
}

// ---------------- fused GIN layer: gather + 2-GEMM MLP, all in one kernel ----------------
// Reads activations from abuf(SRCB); writes abuf(DSTB) (fp16) or g_x (fp32).
// Double-buffered across layers: a layer NEVER writes the buffer it gathers from
// (the gather has all-to-all row dependence -> same-buffer fusion races).
// Phase 0: agg_r = ((1+eps)*src_r + sum_{j in N(r)} src_j) / SCL -> smem AGG (fp16)
// Phase 1: mid = relu(AGG*SCL @ Wa + ba) / SCL -> smem Mid (fp16)
// Phase 2: out = relu(Mid*SCL @ Wb + bb) -> dst
// 256 threads, BM=128, warp grid 4(m) x 2(n). Dynamic smem.
template <int K1, int H, int HOUT, int WOFFA, int WOFFB, int SRCB, int DSTB, bool HALF_OUT>
__global__ __launch_bounds__(256) void k_layer(const float* __restrict__ epsp,
                                               const float* __restrict__ Ba,
                                               const float* __restrict__ Bb) {
    const int BM = 128;
    const int APAD = K1 + 8;                 // AGG row stride (halfs), 16B aligned
    const int BPAD = H + 8;                  // W tile / Mid row stride (halfs)
    const int WN = (H == 128) ? 64 : 32;     // warp n width
    const int NT = WN / 8;                   // 8 or 4
    const int NP = NT / 2;                   // 4 or 2

    extern __shared__ __align__(16) __half smem[];
    __half (*AGG)[APAD] = (__half(*)[APAD])smem;                           // BM x APAD
    __half (*Bs)[BPAD]  = (__half(*)[BPAD])(smem + BM * APAD);             // 16 x BPAD
    __half (*Mid)[BPAD] = (__half(*)[BPAD])(smem + BM * APAD + 16 * BPAD); // BM x BPAD

    const __half* SRC = abuf(SRCB);
    const __half* Wa = g_wh + WOFFA;
    const __half* Wb = g_wh + WOFFB;

    int tid = threadIdx.x;
    int wid = tid >> 5, lane = tid & 31;
    int warp_m = wid & 3;
    int warp_n = wid >> 2;
    int row0 = blockIdx.x * BM;
    int qid = lane >> 2;     // epilogue row within 8
    int tq = lane & 3;       // epilogue col pair

    // ---------------- phase 0: gather into AGG (warp-per-node, 16 nodes/warp) ----------------
    {
        float scale = 1.0f + __ldg(epsp);
        for (int i = 0; i < 16; i++) {
            int r = wid * 16 + i;            // 0..127
            int node = row0 + r;
            if (node < NN) {
                int start = g_off[node];
                int end = g_cur[node];
                if (start < 0) start = 0;
                if (end > EE) end = EE;
                if (end < start) end = start;
                if (K1 == 128) {
                    const uint2* xh = (const uint2*)SRC;    // 4 halfs/lane, row = 32 uint2
                    uint2 sv = xh[node * 32 + lane];
                    float2 s0 = __half22float2(*reinterpret_cast<__half2*>(&sv.x));
                    float2 s1 = __half22float2(*reinterpret_cast<__half2*>(&sv.y));
                    float4 acc = make_float4(s0.x * scale, s0.y * scale,
                                             s1.x * scale, s1.y * scale);
                    for (int j = start; j < end; j++) {
                        uint2 v = xh[g_csr[j] * 32 + lane];
                        float2 f0 = __half22float2(*reinterpret_cast<__half2*>(&v.x));
                        float2 f1 = __half22float2(*reinterpret_cast<__half2*>(&v.y));
                        acc.x += f0.x; acc.y += f0.y; acc.z += f1.x; acc.w += f1.y;
                    }
                    __half2 o0 = __floats2half2_rn(acc.x * SCLI, acc.y * SCLI);
                    __half2 o1 = __floats2half2_rn(acc.z * SCLI, acc.w * SCLI);
                    *(__half2*)&AGG[r][lane * 4]     = o0;
                    *(__half2*)&AGG[r][lane * 4 + 2] = o1;
                } else {                                    // K1 == 64: 2 halfs/lane
                    const __half2* xh = (const __half2*)SRC;
                    float2 s = __half22float2(xh[node * 32 + lane]);
                    float2 acc = make_float2(s.x * scale, s.y * scale);
                    for (int j = start; j < end; j++) {
                        float2 f = __half22float2(xh[g_csr[j] * 32 + lane]);
                        acc.x += f.x; acc.y += f.y;
                    }
                    *(__half2*)&AGG[r][lane * 2] = __floats2half2_rn(acc.x * SCLI, acc.y * SCLI);
                }
            } else {
                // zero-fill out-of-range rows: mma must never read unwritten smem
                if (K1 == 128) {
                    *(__half2*)&AGG[r][lane * 4]     = __floats2half2_rn(0.f, 0.f);
                    *(__half2*)&AGG[r][lane * 4 + 2] = __floats2half2_rn(0.f, 0.f);
                } else {
                    *(__half2*)&AGG[r][lane * 2] = __floats2half2_rn(0.f, 0.f);
                }
            }
        }
    }
    __syncthreads();

    // ---------------- phase 1: mid = relu(AGG*SCL @ Wa + ba) -> Mid ----------------
    {
        float acc[2][NT][4];
        #pragma unroll
        for (int tm = 0; tm < 2; tm++)
            #pragma unroll
            for (int tn = 0; tn < NT; tn++)
                #pragma unroll
                for (int q = 0; q < 4; q++) acc[tm][tn][q] = 0.0f;

        for (int k0 = 0; k0 < K1; k0 += 16) {
            // Wa tile: 16 x H halfs
            if (H == 128) {
                int rk = tid >> 4, c8 = tid & 15;
                *(uint4*)&Bs[rk][c8 * 8] = *(const uint4*)&Wa[(k0 + rk) * H + c8 * 8];
            } else if (tid < 128) {
                int rk = tid >> 3, c8 = tid & 7;
                *(uint4*)&Bs[rk][c8 * 8] = *(const uint4*)&Wa[(k0 + rk) * H + c8 * 8];
            }
            __syncthreads();

            uint32_t a[2][4];
            #pragma unroll
            for (int tm = 0; tm < 2; tm++) {
                const __half* p = &AGG[warp_m * 32 + tm * 16 + (lane & 15)]
                                      [k0 + (lane >> 4) * 8];
                uint32_t ad = (uint32_t)__cvta_generic_to_shared(p);
                asm volatile("ldmatrix.sync.aligned.m8n8.x4.shared.b16 {%0,%1,%2,%3}, [%4];"
                             : "=r"(a[tm][0]), "=r"(a[tm][1]), "=r"(a[tm][2]), "=r"(a[tm][3])
                             : "r"(ad));
            }
            #pragma unroll
            for (int np = 0; np < NP; np++) {
                uint32_t b[4];
                const __half* p = &Bs[lane & 15][warp_n * WN + np * 16 + (lane >> 4) * 8];
                uint32_t ad = (uint32_t)__cvta_generic_to_shared(p);
                asm volatile("ldmatrix.sync.aligned.m8n8.x4.trans.shared.b16 {%0,%1,%2,%3}, [%4];"
                             : "=r"(b[0]), "=r"(b[1]), "=r"(b[2]), "=r"(b[3])
                             : "r"(ad));
                #pragma unroll
                for (int tm = 0; tm < 2; tm++) {
                    asm volatile(
                        "mma.sync.aligned.m16n8k16.row.col.f32.f16.f16.f32 "
                        "{%0,%1,%2,%3}, {%4,%5,%6,%7}, {%8,%9}, {%0,%1,%2,%3};"
                        : "+f"(acc[tm][np * 2][0]), "+f"(acc[tm][np * 2][1]),
                          "+f"(acc[tm][np * 2][2]), "+f"(acc[tm][np * 2][3])
                        : "r"(a[tm][0]), "r"(a[tm][1]), "r"(a[tm][2]), "r"(a[tm][3]),
                          "r"(b[0]), "r"(b[1]));
                    asm volatile(
                        "mma.sync.aligned.m16n8k16.row.col.f32.f16.f16.f32 "
                        "{%0,%1,%2,%3}, {%4,%5,%6,%7}, {%8,%9}, {%0,%1,%2,%3};"
                        : "+f"(acc[tm][np * 2 + 1][0]), "+f"(acc[tm][np * 2 + 1][1]),
                          "+f"(acc[tm][np * 2 + 1][2]), "+f"(acc[tm][np * 2 + 1][3])
                        : "r"(a[tm][0]), "r"(a[tm][1]), "r"(a[tm][2]), "r"(a[tm][3]),
                          "r"(b[2]), "r"(b[3]));
                }
            }
            __syncthreads();
        }

        #pragma unroll
        for (int tm = 0; tm < 2; tm++) {
            #pragma unroll
            for (int tn = 0; tn < NT; tn++) {
                int c = warp_n * WN + tn * 8 + tq * 2;
                float2 bb = *(const float2*)&Ba[c];
                #pragma unroll
                for (int h = 0; h < 2; h++) {
                    int rr = warp_m * 32 + tm * 16 + qid + h * 8;
                    float v0 = fmaxf(acc[tm][tn][h * 2 + 0] * SCL + bb.x, 0.0f);
                    float v1 = fmaxf(acc[tm][tn][h * 2 + 1] * SCL + bb.y, 0.0f);
                    *(__half2*)&Mid[rr][c] = __floats2half2_rn(v0 * SCLI, v1 * SCLI);
                }
            }
        }
    }
    __syncthreads();

    // ---------------- phase 2: out = relu(Mid*SCL @ Wb + bb) ----------------
    {
        float acc[2][NT][4];
        #pragma unroll
        for (int tm = 0; tm < 2; tm++)
            #pragma unroll
            for (int tn = 0; tn < NT; tn++)
                #pragma unroll
                for (int q = 0; q < 4; q++) acc[tm][tn][q] = 0.0f;

        for (int k0 = 0; k0 < H; k0 += 16) {
            if (HOUT == 128) {
                int rk = tid >> 4, c8 = tid & 15;
                *(uint4*)&Bs[rk][c8 * 8] = *(const uint4*)&Wb[(k0 + rk) * HOUT + c8 * 8];
            } else if (tid < 128) {
                int rk = tid >> 3, c8 = tid & 7;
                *(uint4*)&Bs[rk][c8 * 8] = *(const uint4*)&Wb[(k0 + rk) * HOUT + c8 * 8];
            }
            __syncthreads();

            uint32_t a[2][4];
            #pragma unroll
            for (int tm = 0; tm < 2; tm++) {
                const __half* p = &Mid[warp_m * 32 + tm * 16 + (lane & 15)]
                                      [k0 + (lane >> 4) * 8];
                uint32_t ad = (uint32_t)__cvta_generic_to_shared(p);
                asm volatile("ldmatrix.sync.aligned.m8n8.x4.shared.b16 {%0,%1,%2,%3}, [%4];"
                             : "=r"(a[tm][0]), "=r"(a[tm][1]), "=r"(a[tm][2]), "=r"(a[tm][3])
                             : "r"(ad));
            }
            #pragma unroll
            for (int np = 0; np < NP; np++) {
                uint32_t b[4];
                const __half* p = &Bs[lane & 15][warp_n * WN + np * 16 + (lane >> 4) * 8];
                uint32_t ad = (uint32_t)__cvta_generic_to_shared(p);
                asm volatile("ldmatrix.sync.aligned.m8n8.x4.trans.shared.b16 {%0,%1,%2,%3}, [%4];"
                             : "=r"(b[0]), "=r"(b[1]), "=r"(b[2]), "=r"(b[3])
                             : "r"(ad));
                #pragma unroll
                for (int tm = 0; tm < 2; tm++) {
                    asm volatile(
                        "mma.sync.aligned.m16n8k16.row.col.f32.f16.f16.f32 "
                        "{%0,%1,%2,%3}, {%4,%5,%6,%7}, {%8,%9}, {%0,%1,%2,%3};"
                        : "+f"(acc[tm][np * 2][0]), "+f"(acc[tm][np * 2][1]),
                          "+f"(acc[tm][np * 2][2]), "+f"(acc[tm][np * 2][3])
                        : "r"(a[tm][0]), "r"(a[tm][1]), "r"(a[tm][2]), "r"(a[tm][3]),
                          "r"(b[0]), "r"(b[1]));
                    asm volatile(
                        "mma.sync.aligned.m16n8k16.row.col.f32.f16.f16.f32 "
                        "{%0,%1,%2,%3}, {%4,%5,%6,%7}, {%8,%9}, {%0,%1,%2,%3};"
                        : "+f"(acc[tm][np * 2 + 1][0]), "+f"(acc[tm][np * 2 + 1][1]),
                          "+f"(acc[tm][np * 2 + 1][2]), "+f"(acc[tm][np * 2 + 1][3])
                        : "r"(a[tm][0]), "r"(a[tm][1]), "r"(a[tm][2]), "r"(a[tm][3]),
                          "r"(b[2]), "r"(b[3]));
                }
            }
            __syncthreads();
        }

        #pragma unroll
        for (int tm = 0; tm < 2; tm++) {
            #pragma unroll
            for (int tn = 0; tn < NT; tn++) {
                int c = warp_n * WN + tn * 8 + tq * 2;
                float2 bb = *(const float2*)&Bb[c];
                #pragma unroll
                for (int h = 0; h < 2; h++) {
                    int r = row0 + warp_m * 32 + tm * 16 + qid + h * 8;
                    if (r < NN) {
                        float v0 = fmaxf(acc[tm][tn][h * 2 + 0] * SCL + bb.x, 0.0f);
                        float v1 = fmaxf(acc[tm][tn][h * 2 + 1] * SCL + bb.y, 0.0f);
                        if (HALF_OUT) {
                            *(__half2*)&abuf(DSTB)[r * HOUT + c] = __floats2half2_rn(v0, v1);
                        } else {
                            *(float2*)&g_x[r * HOUT + c] = make_float2(v0, v1);
                        }
                    }
                }
            }
        }
    }
}

// ---------------- final FC (N,64)@(64,8)+b and emb copy ----------------
__global__ void k_fc(const float* __restrict__ W,
                     const float* __restrict__ B,
                     float* __restrict__ out,
                     float* __restrict__ emb) {
    int gw = (blockIdx.x * blockDim.x + threadIdx.x) >> 5;
    if (gw >= NN) return;
    int lane = threadIdx.x & 31;
    float v0 = g_x[gw * 64 + lane];
    float v1 = g_x[gw * 64 + 32 + lane];
    emb[gw * 64 + lane] = v0;
    emb[gw * 64 + 32 + lane] = v1;
    #pragma unroll
    for (int j = 0; j < 8; j++) {
        float p = v0 * W[lane * 8 + j] + v1 * W[(lane + 32) * 8 + j];
        #pragma unroll
        for (int o = 16; o > 0; o >>= 1)
            p += __shfl_down_sync(0xffffffffu, p, o);
        if (lane == 0) out[gw * 8 + j] = p + B[j];
    }
}

// ---------------- launch ----------------
extern "C" void kernel_launch(void* const* d_in, const int* in_sizes, int n_in,
                              void* d_out, int out_size) {
    const float* x    = (const float*)d_in[0];
    const void*  ei   = d_in[1];
    const float* eps1 = (const float*)d_in[2];
    const float* eps2 = (const float*)d_in[3];
    const float* eps3 = (const float*)d_in[4];
    const float* W1a  = (const float*)d_in[5];
    const float* b1a  = (const float*)d_in[6];
    const float* W1b  = (const float*)d_in[7];
    const float* b1b  = (const float*)d_in[8];
    const float* W2a  = (const float*)d_in[9];
    const float* b2a  = (const float*)d_in[10];
    const float* W2b  = (const float*)d_in[11];
    const float* b2b  = (const float*)d_in[12];
    const float* W3a  = (const float*)d_in[13];
    const float* b3a  = (const float*)d_in[14];
    const float* W3b  = (const float*)d_in[15];
    const float* b3b  = (const float*)d_in[16];
    const float* Wfc  = (const float*)d_in[17];
    const float* bfc  = (const float*)d_in[18];

    float* out = (float*)d_out;             // (N, 8)
    float* emb = out + NN * 8;              // (N, 64)

    // dynamic smem sizes: AGG (128 x K1+8) + Bs (16 x H+8) + Mid (128 x H+8), halfs
    const int smem1 = (128 * (64 + 8) + 16 * (128 + 8) + 128 * (128 + 8)) * 2;   // 57600
    const int smem2 = (128 * (128 + 8) + 16 * (128 + 8) + 128 * (128 + 8)) * 2;  // 73984
    const int smem3 = (128 * (128 + 8) + 16 * (64 + 8) + 128 * (64 + 8)) * 2;    // 55552
    cudaFuncSetAttribute((const void*)k_layer<64, 128, 128, 0, 8192, 0, 1, true>,
                         cudaFuncAttributeMaxDynamicSharedMemorySize, smem1);
    cudaFuncSetAttribute((const void*)k_layer<128, 128, 128, 24576, 40960, 1, 0, true>,
                         cudaFuncAttributeMaxDynamicSharedMemorySize, smem2);
    cudaFuncSetAttribute((const void*)k_layer<128, 64, 64, 57344, 65536, 0, 0, false>,
                         cudaFuncAttributeMaxDynamicSharedMemorySize, smem3);

    // CSR build
    k_detect<<<(NN + 1023) / 1024, 1024>>>((const long long*)ei);
    k_hist<<<(EE + 255) / 256, 256>>>(ei);
    k_block_sums<<<SCAN_NB, SCAN_BLK>>>();
    k_scan_parts<<<1, 128>>>();
    k_scan_final<<<SCAN_NB, SCAN_BLK>>>();
    k_fill<<<(EE + 255) / 256, 256>>>(ei);

    // fp16 conversions
    k_x2h<<<(NN * 32 + 255) / 256, 256>>>(x);
    k_w2h<<<(69632 + 255) / 256, 256>>>(W1a, W1b, W2a, W2b, W3a, W3b);

    const int aggBlocks = (NN * 32 + 255) / 256;
    const int gemmBlocks = (NN + 127) / 128;

    // Weight offsets in g_wh: W1a=0 W1b=8192 W2a=24576 W2b=40960 W3a=57344 W3b=65536
    // Fused layers, double-buffered activations: L1 xh->yh, L2 yh->xh, L3 xh->g_x.
    k_layer<64, 128, 128, 0, 8192, 0, 1, true><<<gemmBlocks, 256, smem1>>>(eps1, b1a, b1b);
    k_layer<128, 128, 128, 24576, 40960, 1, 0, true><<<gemmBlocks, 256, smem2>>>(eps2, b2a, b2b);
    k_layer<128, 64, 64, 57344, 65536, 0, 0, false><<<gemmBlocks, 256, smem3>>>(eps3, b3a, b3b);

    // FC + emb
    k_fc<<<aggBlocks, 256>>>(Wfc, bfc, out, emb);
}